// round 10
// baseline (speedup 1.0000x reference)
#include <cuda_runtime.h>
#include <cuda_bf16.h>
#include <cstdint>
#include <cstddef>

#define N_NODES 50000
#define N_EDGES 600000
#define F 128

// ---------------- scratch (static device globals) ----------------------------
__device__ int   g_deg[N_NODES];
__device__ int   g_start[N_NODES];
__device__ int   g_pos[N_NODES];
__device__ float g_inv[N_NODES];
__device__ int   g_elist[N_EDGES];
__device__ int   g_total;

__device__ __align__(16) __nv_bfloat16 g_a0hi[N_NODES * F];
__device__ __align__(16) __nv_bfloat16 g_a0lo[N_NODES * F];
__device__ __align__(16) __nv_bfloat16 g_a1hi[N_NODES * F];
__device__ __align__(16) __nv_bfloat16 g_a1lo[N_NODES * F];
__device__ __align__(16) __nv_bfloat16 g_a2hi[N_NODES * F];
__device__ __align__(16) __nv_bfloat16 g_a2lo[N_NODES * F];
__device__ __align__(16) __nv_bfloat16 g_mhi[N_NODES * F];
__device__ __align__(16) __nv_bfloat16 g_mlo[N_NODES * F];
__device__ __align__(16) __nv_bfloat16 g_wts[12 * F * F];  // per layer: Wshi,Wslo,Wnhi,Wnlo

// ---------------- helpers ----------------------------------------------------
__device__ __forceinline__ uint32_t smem_u32(const void* p) {
    uint32_t a;
    asm("{ .reg .u64 t; cvta.to.shared.u64 t, %1; cvt.u32.u64 %0, t; }" : "=r"(a) : "l"(p));
    return a;
}
__device__ __forceinline__ void cp_async16(uint32_t dst, const void* src, uint32_t pbytes) {
    asm volatile("cp.async.cg.shared.global [%0], [%1], 16, %2;"
                 :: "r"(dst), "l"(src), "r"(pbytes));
}
__device__ __forceinline__ void cp_commit() { asm volatile("cp.async.commit_group;"); }
template <int N>
__device__ __forceinline__ void cp_wait() { asm volatile("cp.async.wait_group %0;" :: "n"(N)); }

__device__ __forceinline__ void ldm_x4(uint32_t* r, uint32_t addr) {
    asm volatile("ldmatrix.sync.aligned.m8n8.x4.shared.b16 {%0,%1,%2,%3}, [%4];"
                 : "=r"(r[0]), "=r"(r[1]), "=r"(r[2]), "=r"(r[3]) : "r"(addr));
}
__device__ __forceinline__ void mma_bf16(float* d, const uint32_t* a, uint32_t b0, uint32_t b1) {
    asm volatile("mma.sync.aligned.m16n8k16.row.col.f32.bf16.bf16.f32 "
                 "{%0,%1,%2,%3}, {%4,%5,%6,%7}, {%8,%9}, {%0,%1,%2,%3};"
                 : "+f"(d[0]), "+f"(d[1]), "+f"(d[2]), "+f"(d[3])
                 : "r"(a[0]), "r"(a[1]), "r"(a[2]), "r"(a[3]), "r"(b0), "r"(b1));
}

// ---------------- fp32 -> bf16 hi/lo split -----------------------------------
__device__ __forceinline__ void split1(float v, __nv_bfloat16& h, __nv_bfloat16& l) {
    h = __float2bfloat16_rn(v);
    l = __float2bfloat16_rn(v - __bfloat162float(h));
}

// ---------------- launch 1: zero deg + split features ------------------------
__global__ void fuse_zero_split_kernel(const float* __restrict__ x,
                                       __nv_bfloat16* __restrict__ hi,
                                       __nv_bfloat16* __restrict__ lo) {
    int i = blockIdx.x * blockDim.x + threadIdx.x;
    if (i < N_NODES) g_deg[i] = 0;
    if (i == 0) g_total = 0;
    const int n4 = N_NODES * F / 4;
    if (i < n4) {
        float4 v = ((const float4*)x)[i];
        __align__(8) __nv_bfloat16 h[4], l[4];
        split1(v.x, h[0], l[0]); split1(v.y, h[1], l[1]);
        split1(v.z, h[2], l[2]); split1(v.w, h[3], l[3]);
        ((uint2*)hi)[i] = *(uint2*)h;
        ((uint2*)lo)[i] = *(uint2*)l;
    }
}

// ---------------- launch 2: degree count (ILP4) + weight prep ----------------
__global__ void fuse_count_prep_kernel(const int* __restrict__ dst,
                                       const float* __restrict__ W0, const float* __restrict__ W1,
                                       const float* __restrict__ W2, const float* __restrict__ W3,
                                       const float* __restrict__ W4, const float* __restrict__ W5,
                                       __nv_bfloat16* __restrict__ wts) {
    int i = blockIdx.x * blockDim.x + threadIdx.x;
    int e0 = i * 4;
    if (e0 + 3 < N_EDGES) {
        int4 d4 = *(const int4*)(dst + e0);
        atomicAdd(&g_deg[d4.x], 1);
        atomicAdd(&g_deg[d4.y], 1);
        atomicAdd(&g_deg[d4.z], 1);
        atomicAdd(&g_deg[d4.w], 1);
    } else if (e0 < N_EDGES) {
        for (int e = e0; e < N_EDGES; e++) atomicAdd(&g_deg[dst[e]], 1);
    }
    if (i < 6 * F * F) {
        int w = i / (F * F), r = i % (F * F);
        int n = r >> 7, k = r & 127;
        const float* Wp[6] = {W0, W1, W2, W3, W4, W5};
        float v = Wp[w][k * F + n];
        __nv_bfloat16 h, l;
        split1(v, h, l);
        int layer = w >> 1, sn = w & 1;
        size_t base = ((size_t)layer * 4 + sn * 2) * F * F;
        wts[base + r]         = h;
        wts[base + F * F + r] = l;
    }
}

// ---------------- launch 3: CSR bucket starts --------------------------------
__global__ void assign_start_kernel() {
    int i = blockIdx.x * blockDim.x + threadIdx.x;
    if (i >= N_NODES) return;
    int d = g_deg[i];
    int s = atomicAdd(&g_total, d);
    g_start[i] = s;
    g_pos[i]   = s;
    g_inv[i]   = 1.0f / fmaxf((float)d, 1.0f);
}

// ---------------- launch 4 (profiled): edge bucket fill (ILP4) ---------------
__global__ void fill_edges_kernel(const int* __restrict__ src, const int* __restrict__ dst) {
    int i = blockIdx.x * blockDim.x + threadIdx.x;
    int e0 = i * 4;
    if (e0 + 3 < N_EDGES) {
        int4 d4 = *(const int4*)(dst + e0);
        int4 s4 = *(const int4*)(src + e0);
        int p0 = atomicAdd(&g_pos[d4.x], 1);
        int p1 = atomicAdd(&g_pos[d4.y], 1);
        int p2 = atomicAdd(&g_pos[d4.z], 1);
        int p3 = atomicAdd(&g_pos[d4.w], 1);
        g_elist[p0] = s4.x;
        g_elist[p1] = s4.y;
        g_elist[p2] = s4.z;
        g_elist[p3] = s4.w;
    } else if (e0 < N_EDGES) {
        for (int e = e0; e < N_EDGES; e++) {
            int p = atomicAdd(&g_pos[dst[e]], 1);
            g_elist[p] = src[e];
        }
    }
}

// ---------------- mean aggregation (warp per node) ---------------------------
__global__ void agg_f32_kernel(const float* __restrict__ x) {
    int w    = (blockIdx.x * blockDim.x + threadIdx.x) >> 5;
    int lane = threadIdx.x & 31;
    if (w >= N_NODES) return;
    int s0 = g_start[w];
    int d  = g_deg[w];
    int co = lane * 4;
    float a0 = 0.f, a1 = 0.f, a2 = 0.f, a3 = 0.f;
    for (int j = 0; j < d; j++) {
        int s = g_elist[s0 + j];
        float4 v = *(const float4*)(x + (size_t)s * F + co);
        a0 += v.x; a1 += v.y; a2 += v.z; a3 += v.w;
    }
    float iv = g_inv[w];
    __align__(8) __nv_bfloat16 h[4], l[4];
    split1(a0 * iv, h[0], l[0]); split1(a1 * iv, h[1], l[1]);
    split1(a2 * iv, h[2], l[2]); split1(a3 * iv, h[3], l[3]);
    *(uint2*)(g_mhi + (size_t)w * F + co) = *(uint2*)h;
    *(uint2*)(g_mlo + (size_t)w * F + co) = *(uint2*)l;
}

__global__ void agg_bf16_kernel(const __nv_bfloat16* __restrict__ xhi,
                                const __nv_bfloat16* __restrict__ xlo) {
    int w    = (blockIdx.x * blockDim.x + threadIdx.x) >> 5;
    int lane = threadIdx.x & 31;
    if (w >= N_NODES) return;
    int s0 = g_start[w];
    int d  = g_deg[w];
    int co = lane * 4;
    float a0 = 0.f, a1 = 0.f, a2 = 0.f, a3 = 0.f;
    for (int j = 0; j < d; j++) {
        int s = g_elist[s0 + j];
        uint2 uh = *(const uint2*)(xhi + (size_t)s * F + co);
        uint2 ul = *(const uint2*)(xlo + (size_t)s * F + co);
        float2 h0 = __bfloat1622float2(*(__nv_bfloat162*)&uh.x);
        float2 h1 = __bfloat1622float2(*(__nv_bfloat162*)&uh.y);
        float2 l0 = __bfloat1622float2(*(__nv_bfloat162*)&ul.x);
        float2 l1 = __bfloat1622float2(*(__nv_bfloat162*)&ul.y);
        a0 += h0.x + l0.x; a1 += h0.y + l0.y;
        a2 += h1.x + l1.x; a3 += h1.y + l1.y;
    }
    float iv = g_inv[w];
    __align__(8) __nv_bfloat16 h[4], l[4];
    split1(a0 * iv, h[0], l[0]); split1(a1 * iv, h[1], l[1]);
    split1(a2 * iv, h[2], l[2]); split1(a3 * iv, h[3], l[3]);
    *(uint2*)(g_mhi + (size_t)w * F + co) = *(uint2*)h;
    *(uint2*)(g_mlo + (size_t)w * F + co) = *(uint2*)l;
}

// ---------------- dual-GEMM, 128x64 tile, 3 blocks/SM ------------------------
// block tile: 128 rows x 64 cols; 8 warps as 4(m) x 2(n); warp tile 32x32.
// stage: A 16KB (128r x 64k) + B 8KB (64n x 64k) = 24KB; 3 stages = 72KB.
// K_eff = 6 segments x 128 = 768, 12 K=64 chunks.
#define STAGE_BYTES 24576
#define NSTAGE 3
#define DK_NCHUNK 12
__global__ void __launch_bounds__(256, 3)
sage_dual_gemm(const __nv_bfloat16* __restrict__ Ahi,
               const __nv_bfloat16* __restrict__ Alo,
               const __nv_bfloat16* __restrict__ Mhi,
               const __nv_bfloat16* __restrict__ Mlo,
               const __nv_bfloat16* __restrict__ Wb,   // Wshi,Wslo,Wnhi,Wnlo ([n][k])
               const float* __restrict__ bias,
               __nv_bfloat16* __restrict__ Ohi,
               __nv_bfloat16* __restrict__ Olo,
               float* __restrict__ Ofp,
               int do_relu, int write_fp) {
    extern __shared__ __align__(16) char sm[];
    __shared__ float s_bias[64];

    int tid = threadIdx.x, lane = tid & 31, wid = tid >> 5;
    int warp_m = wid & 3, warp_n = wid >> 2;
    int row0 = (blockIdx.x >> 1) * 128;
    int col0 = (blockIdx.x & 1) * 64;

    if (tid < 64) s_bias[tid] = bias[col0 + tid];

    const __nv_bfloat16* Aptr[4] = {Ahi, Alo, Mhi, Mlo};
    const int AI[6] = {0, 0, 1, 2, 2, 3};
    const int BI[6] = {0, 1, 0, 2, 3, 2};
    uint32_t smb = smem_u32(sm);

    float acc[2][4][4];
#pragma unroll
    for (int i = 0; i < 2; i++)
#pragma unroll
        for (int j = 0; j < 4; j++)
#pragma unroll
            for (int k = 0; k < 4; k++) acc[i][j][k] = 0.f;

    auto load_chunk = [&](int c, int stg) {
        int seg = c >> 1;
        int kc  = (c & 1) * 64;
        const __nv_bfloat16* Ag = Aptr[AI[seg]];
        const __nv_bfloat16* Bg = Wb + (size_t)BI[seg] * F * F;
        uint32_t aB = smb + stg * STAGE_BYTES;
        uint32_t bB = aB + 16384;
        // A: 128 rows x 128B -> 1024 quads
#pragma unroll
        for (int i = 0; i < 4; i++) {
            int idx = tid + i * 256;
            int row = idx >> 3, q = idx & 7;
            uint32_t sw = (uint32_t)(row * 128 + ((q ^ (row & 7)) * 16));
            int gr = row0 + row;
            int grc = (gr < N_NODES) ? gr : 0;
            uint32_t p = (gr < N_NODES) ? 16u : 0u;
            cp_async16(aB + sw, Ag + (size_t)grc * F + kc + q * 8, p);
        }
        // B: 64 n-rows x 128B -> 512 quads
#pragma unroll
        for (int i = 0; i < 2; i++) {
            int idx = tid + i * 256;
            int row = idx >> 3, q = idx & 7;
            uint32_t sw = (uint32_t)(row * 128 + ((q ^ (row & 7)) * 16));
            cp_async16(bB + sw, Bg + (size_t)(col0 + row) * F + kc + q * 8, 16u);
        }
        cp_commit();
    };

    auto compute = [&](int stg) {
        uint32_t aB = smb + stg * STAGE_BYTES;
        uint32_t bB = aB + 16384;
#pragma unroll
        for (int ks = 0; ks < 64; ks += 16) {
            uint32_t af[2][4];
#pragma unroll
            for (int ms = 0; ms < 2; ms++) {
                int r = warp_m * 32 + ms * 16 + (lane & 15);
                int q = (ks >> 3) + (lane >> 4);
                ldm_x4(af[ms], aB + r * 128 + ((q ^ (r & 7)) * 16));
            }
            uint32_t bf[2][4];
#pragma unroll
            for (int np = 0; np < 2; np++) {
                int n = warp_n * 32 + np * 16 + (lane & 7) + ((lane >> 4) << 3);
                int q = (ks >> 3) + ((lane >> 3) & 1);
                ldm_x4(bf[np], bB + n * 128 + ((q ^ (n & 7)) * 16));
            }
#pragma unroll
            for (int ms = 0; ms < 2; ms++)
#pragma unroll
                for (int np = 0; np < 2; np++) {
                    mma_bf16(acc[ms][np * 2 + 0], af[ms], bf[np][0], bf[np][1]);
                    mma_bf16(acc[ms][np * 2 + 1], af[ms], bf[np][2], bf[np][3]);
                }
        }
    };

    load_chunk(0, 0);
    load_chunk(1, 1);
    for (int c = 0; c < DK_NCHUNK; c++) {
        if (c + 1 < DK_NCHUNK) cp_wait<1>(); else cp_wait<0>();
        __syncthreads();
        if (c + 2 < DK_NCHUNK) load_chunk(c + 2, (c + 2) % NSTAGE);
        compute(c % NSTAGE);
    }

#pragma unroll
    for (int ms = 0; ms < 2; ms++) {
#pragma unroll
        for (int half = 0; half < 2; half++) {
            int gr = row0 + warp_m * 32 + ms * 16 + (lane >> 2) + half * 8;
            if (gr >= N_NODES) continue;
#pragma unroll
            for (int np = 0; np < 4; np++) {
                int cl = warp_n * 32 + np * 8 + (lane & 3) * 2;
                float v0 = acc[ms][np][half * 2 + 0] + s_bias[cl];
                float v1 = acc[ms][np][half * 2 + 1] + s_bias[cl + 1];
                if (do_relu) { v0 = fmaxf(v0, 0.f); v1 = fmaxf(v1, 0.f); }
                size_t gi = (size_t)gr * F + col0 + cl;
                if (write_fp) {
                    *(float2*)(Ofp + gi) = make_float2(v0, v1);
                } else {
                    __nv_bfloat16 h0, l0, h1, l1;
                    split1(v0, h0, l0); split1(v1, h1, l1);
                    __nv_bfloat162 hh; hh.x = h0; hh.y = h1;
                    __nv_bfloat162 ll; ll.x = l0; ll.y = l1;
                    *(__nv_bfloat162*)(Ohi + gi) = hh;
                    *(__nv_bfloat162*)(Olo + gi) = ll;
                }
            }
        }
    }
}

// ---------------- launch -----------------------------------------------------
extern "C" void kernel_launch(void* const* d_in, const int* in_sizes, int n_in,
                              void* d_out, int out_size) {
    const float* feat = (const float*)d_in[0];
    const int*   src  = (const int*)d_in[1];
    const int*   dst  = (const int*)d_in[2];
    const float* Wsl[3] = {(const float*)d_in[3], (const float*)d_in[6], (const float*)d_in[9]};
    const float* Wnl[3] = {(const float*)d_in[4], (const float*)d_in[7], (const float*)d_in[10]};
    const float* bl[3]  = {(const float*)d_in[5], (const float*)d_in[8], (const float*)d_in[11]};
    float* out = (float*)d_out;

    __nv_bfloat16 *a0hi, *a0lo, *a1hi, *a1lo, *a2hi, *a2lo, *mhi, *mlo, *wts;
    cudaGetSymbolAddress((void**)&a0hi, g_a0hi);
    cudaGetSymbolAddress((void**)&a0lo, g_a0lo);
    cudaGetSymbolAddress((void**)&a1hi, g_a1hi);
    cudaGetSymbolAddress((void**)&a1lo, g_a1lo);
    cudaGetSymbolAddress((void**)&a2hi, g_a2hi);
    cudaGetSymbolAddress((void**)&a2lo, g_a2lo);
    cudaGetSymbolAddress((void**)&mhi,  g_mhi);
    cudaGetSymbolAddress((void**)&mlo,  g_mlo);
    cudaGetSymbolAddress((void**)&wts,  g_wts);

    const int DSM = NSTAGE * STAGE_BYTES;  // 72KB
    cudaFuncSetAttribute(sage_dual_gemm, cudaFuncAttributeMaxDynamicSharedMemorySize, DSM);

    const int TB = 256;
    const int aggGrid = (N_NODES * 32 + TB - 1) / TB;
    const int gmGrid  = ((N_NODES + 127) / 128) * 2;   // 128x64 tiles -> 782
    const int n4 = N_NODES * F / 4;
    const int e4 = (N_EDGES / 4 + TB - 1) / TB;

    // launches 1-5
    fuse_zero_split_kernel<<<(n4 + TB - 1) / TB, TB>>>(feat, a0hi, a0lo);
    fuse_count_prep_kernel<<<e4, TB>>>(dst, Wsl[0], Wnl[0], Wsl[1], Wnl[1], Wsl[2], Wnl[2], wts);
    assign_start_kernel<<<(N_NODES + TB - 1) / TB, TB>>>();
    fill_edges_kernel<<<e4, TB>>>(src, dst);   // launch 4 — profiled (ILP4 check)
    agg_f32_kernel<<<aggGrid, TB>>>(feat);

    // layer 1
    sage_dual_gemm<<<gmGrid, 256, DSM>>>(a0hi, a0lo, mhi, mlo, wts + 0 * 4 * F * F,
                                         bl[0], a1hi, a1lo, out, 1, 0);
    // layer 2
    agg_bf16_kernel<<<aggGrid, TB>>>(a1hi, a1lo);
    sage_dual_gemm<<<gmGrid, 256, DSM>>>(a1hi, a1lo, mhi, mlo, wts + 1 * 4 * F * F,
                                         bl[1], a2hi, a2lo, out, 1, 0);
    // layer 3
    agg_bf16_kernel<<<aggGrid, TB>>>(a2hi, a2lo);
    sage_dual_gemm<<<gmGrid, 256, DSM>>>(a2hi, a2lo, mhi, mlo, wts + 2 * 4 * F * F,
                                         bl[2], nullptr, nullptr, out, 0, 1);
}

// round 11
// speedup vs baseline: 1.0664x; 1.0664x over previous
#include <cuda_runtime.h>
#include <cuda_bf16.h>
#include <cstdint>
#include <cstddef>

#define N_NODES 50000
#define N_EDGES 600000
#define F 128

// ---------------- scratch (static device globals) ----------------------------
__device__ int   g_deg[N_NODES];
__device__ int   g_start[N_NODES];
__device__ int   g_pos[N_NODES];
__device__ float g_inv[N_NODES];
__device__ int   g_elist[N_EDGES];
__device__ int   g_total;

__device__ __align__(16) __nv_bfloat16 g_a0hi[N_NODES * F];
__device__ __align__(16) __nv_bfloat16 g_a0lo[N_NODES * F];
__device__ __align__(16) __nv_bfloat16 g_a1hi[N_NODES * F];
__device__ __align__(16) __nv_bfloat16 g_a1lo[N_NODES * F];
__device__ __align__(16) __nv_bfloat16 g_a2hi[N_NODES * F];
__device__ __align__(16) __nv_bfloat16 g_a2lo[N_NODES * F];
__device__ __align__(16) __nv_bfloat16 g_mhi[N_NODES * F];
__device__ __align__(16) __nv_bfloat16 g_mlo[N_NODES * F];
__device__ __align__(16) __nv_bfloat16 g_wts[12 * F * F];  // per layer: Wshi,Wslo,Wnhi,Wnlo

// ---------------- helpers ----------------------------------------------------
__device__ __forceinline__ uint32_t smem_u32(const void* p) {
    uint32_t a;
    asm("{ .reg .u64 t; cvta.to.shared.u64 t, %1; cvt.u32.u64 %0, t; }" : "=r"(a) : "l"(p));
    return a;
}
__device__ __forceinline__ void cp_async16(uint32_t dst, const void* src, uint32_t pbytes) {
    asm volatile("cp.async.cg.shared.global [%0], [%1], 16, %2;"
                 :: "r"(dst), "l"(src), "r"(pbytes));
}
__device__ __forceinline__ void cp_commit() { asm volatile("cp.async.commit_group;"); }
template <int N>
__device__ __forceinline__ void cp_wait() { asm volatile("cp.async.wait_group %0;" :: "n"(N)); }

__device__ __forceinline__ void ldm_x4(uint32_t* r, uint32_t addr) {
    asm volatile("ldmatrix.sync.aligned.m8n8.x4.shared.b16 {%0,%1,%2,%3}, [%4];"
                 : "=r"(r[0]), "=r"(r[1]), "=r"(r[2]), "=r"(r[3]) : "r"(addr));
}
__device__ __forceinline__ void mma_bf16(float* d, const uint32_t* a, uint32_t b0, uint32_t b1) {
    asm volatile("mma.sync.aligned.m16n8k16.row.col.f32.bf16.bf16.f32 "
                 "{%0,%1,%2,%3}, {%4,%5,%6,%7}, {%8,%9}, {%0,%1,%2,%3};"
                 : "+f"(d[0]), "+f"(d[1]), "+f"(d[2]), "+f"(d[3])
                 : "r"(a[0]), "r"(a[1]), "r"(a[2]), "r"(a[3]), "r"(b0), "r"(b1));
}

// ---------------- fp32 -> bf16 hi/lo split -----------------------------------
__device__ __forceinline__ void split1(float v, __nv_bfloat16& h, __nv_bfloat16& l) {
    h = __float2bfloat16_rn(v);
    l = __float2bfloat16_rn(v - __bfloat162float(h));
}

// ---------------- launch 1: zero deg + split features ------------------------
__global__ void fuse_zero_split_kernel(const float* __restrict__ x,
                                       __nv_bfloat16* __restrict__ hi,
                                       __nv_bfloat16* __restrict__ lo) {
    int i = blockIdx.x * blockDim.x + threadIdx.x;
    if (i < N_NODES) g_deg[i] = 0;
    if (i == 0) g_total = 0;
    const int n4 = N_NODES * F / 4;
    if (i < n4) {
        float4 v = ((const float4*)x)[i];
        __align__(8) __nv_bfloat16 h[4], l[4];
        split1(v.x, h[0], l[0]); split1(v.y, h[1], l[1]);
        split1(v.z, h[2], l[2]); split1(v.w, h[3], l[3]);
        ((uint2*)hi)[i] = *(uint2*)h;
        ((uint2*)lo)[i] = *(uint2*)l;
    }
}

// ---------------- launch 2: degree count + weight prep -----------------------
__global__ void fuse_count_prep_kernel(const int* __restrict__ dst,
                                       const float* __restrict__ W0, const float* __restrict__ W1,
                                       const float* __restrict__ W2, const float* __restrict__ W3,
                                       const float* __restrict__ W4, const float* __restrict__ W5,
                                       __nv_bfloat16* __restrict__ wts) {
    int i = blockIdx.x * blockDim.x + threadIdx.x;
    if (i < N_EDGES) atomicAdd(&g_deg[dst[i]], 1);
    if (i < 6 * F * F) {
        int w = i / (F * F), r = i % (F * F);
        int n = r >> 7, k = r & 127;
        const float* Wp[6] = {W0, W1, W2, W3, W4, W5};
        float v = Wp[w][k * F + n];
        __nv_bfloat16 h, l;
        split1(v, h, l);
        int layer = w >> 1, sn = w & 1;
        size_t base = ((size_t)layer * 4 + sn * 2) * F * F;
        wts[base + r]         = h;
        wts[base + F * F + r] = l;
    }
}

// ---------------- launch 3: CSR bucket starts --------------------------------
__global__ void assign_start_kernel() {
    int i = blockIdx.x * blockDim.x + threadIdx.x;
    if (i >= N_NODES) return;
    int d = g_deg[i];
    int s = atomicAdd(&g_total, d);
    g_start[i] = s;
    g_pos[i]   = s;
    g_inv[i]   = 1.0f / fmaxf((float)d, 1.0f);
}

// ---------------- launch 4: edge bucket fill ---------------------------------
__global__ void fill_edges_kernel(const int* __restrict__ src, const int* __restrict__ dst) {
    int e = blockIdx.x * blockDim.x + threadIdx.x;
    if (e < N_EDGES) {
        int p = atomicAdd(&g_pos[dst[e]], 1);
        g_elist[p] = src[e];
    }
}

// ---------------- mean aggregation (warp per node) ---------------------------
__global__ void agg_f32_kernel(const float* __restrict__ x) {
    int w    = (blockIdx.x * blockDim.x + threadIdx.x) >> 5;
    int lane = threadIdx.x & 31;
    if (w >= N_NODES) return;
    int s0 = g_start[w];
    int d  = g_deg[w];
    int co = lane * 4;
    float a0 = 0.f, a1 = 0.f, a2 = 0.f, a3 = 0.f;
    for (int j = 0; j < d; j++) {
        int s = g_elist[s0 + j];
        float4 v = *(const float4*)(x + (size_t)s * F + co);
        a0 += v.x; a1 += v.y; a2 += v.z; a3 += v.w;
    }
    float iv = g_inv[w];
    __align__(8) __nv_bfloat16 h[4], l[4];
    split1(a0 * iv, h[0], l[0]); split1(a1 * iv, h[1], l[1]);
    split1(a2 * iv, h[2], l[2]); split1(a3 * iv, h[3], l[3]);
    *(uint2*)(g_mhi + (size_t)w * F + co) = *(uint2*)h;
    *(uint2*)(g_mlo + (size_t)w * F + co) = *(uint2*)l;
}

__global__ void agg_bf16_kernel(const __nv_bfloat16* __restrict__ xhi,
                                const __nv_bfloat16* __restrict__ xlo) {
    int w    = (blockIdx.x * blockDim.x + threadIdx.x) >> 5;
    int lane = threadIdx.x & 31;
    if (w >= N_NODES) return;
    int s0 = g_start[w];
    int d  = g_deg[w];
    int co = lane * 4;
    float a0 = 0.f, a1 = 0.f, a2 = 0.f, a3 = 0.f;
    for (int j = 0; j < d; j++) {
        int s = g_elist[s0 + j];
        uint2 uh = *(const uint2*)(xhi + (size_t)s * F + co);
        uint2 ul = *(const uint2*)(xlo + (size_t)s * F + co);
        float2 h0 = __bfloat1622float2(*(__nv_bfloat162*)&uh.x);
        float2 h1 = __bfloat1622float2(*(__nv_bfloat162*)&uh.y);
        float2 l0 = __bfloat1622float2(*(__nv_bfloat162*)&ul.x);
        float2 l1 = __bfloat1622float2(*(__nv_bfloat162*)&ul.y);
        a0 += h0.x + l0.x; a1 += h0.y + l0.y;
        a2 += h1.x + l1.x; a3 += h1.y + l1.y;
    }
    float iv = g_inv[w];
    __align__(8) __nv_bfloat16 h[4], l[4];
    split1(a0 * iv, h[0], l[0]); split1(a1 * iv, h[1], l[1]);
    split1(a2 * iv, h[2], l[2]); split1(a3 * iv, h[3], l[3]);
    *(uint2*)(g_mhi + (size_t)w * F + co) = *(uint2*)h;
    *(uint2*)(g_mlo + (size_t)w * F + co) = *(uint2*)l;
}

// ---------------- dual-GEMM (R8 config + per-warp ks stagger) ----------------
// block tile 128x128; 8 warps 4(m)x2(n), warp tile 32x64.
// K_eff = 6 segments x 128 = 768, 12 K=64 chunks, 3-stage cp.async pipeline.
// NEW: warps process the 4 ks-steps of each chunk in rotated order (wid&3)
// so LDSM and MMA phases of different warps interleave instead of lockstep.
#define STAGE_BYTES 32768
#define NSTAGE 3
#define DK_NCHUNK 12
__global__ void __launch_bounds__(256, 2)
sage_dual_gemm(const __nv_bfloat16* __restrict__ Ahi,
               const __nv_bfloat16* __restrict__ Alo,
               const __nv_bfloat16* __restrict__ Mhi,
               const __nv_bfloat16* __restrict__ Mlo,
               const __nv_bfloat16* __restrict__ Wb,   // Wshi,Wslo,Wnhi,Wnlo ([n][k])
               const float* __restrict__ bias,
               __nv_bfloat16* __restrict__ Ohi,
               __nv_bfloat16* __restrict__ Olo,
               float* __restrict__ Ofp,
               int do_relu, int write_fp) {
    extern __shared__ __align__(16) char sm[];
    __shared__ float s_bias[F];

    int tid = threadIdx.x, lane = tid & 31, wid = tid >> 5;
    int warp_m = wid & 3, warp_n = wid >> 2;
    int row0 = blockIdx.x * 128;

    if (tid < F) s_bias[tid] = bias[tid];

    const __nv_bfloat16* Aptr[4] = {Ahi, Alo, Mhi, Mlo};
    const int AI[6] = {0, 0, 1, 2, 2, 3};
    const int BI[6] = {0, 1, 0, 2, 3, 2};
    uint32_t smb = smem_u32(sm);
    int ko = wid & 3;   // per-warp ks-phase offset

    float acc[2][8][4];
#pragma unroll
    for (int i = 0; i < 2; i++)
#pragma unroll
        for (int j = 0; j < 8; j++)
#pragma unroll
            for (int k = 0; k < 4; k++) acc[i][j][k] = 0.f;

    auto load_chunk = [&](int c, int stg) {
        int seg = c >> 1;
        int kc  = (c & 1) * 64;
        const __nv_bfloat16* Ag = Aptr[AI[seg]];
        const __nv_bfloat16* Bg = Wb + (size_t)BI[seg] * F * F;
        uint32_t aB = smb + stg * STAGE_BYTES;
        uint32_t bB = aB + 16384;
#pragma unroll
        for (int i = 0; i < 4; i++) {
            int idx = tid + i * 256;
            int row = idx >> 3, q = idx & 7;
            uint32_t sw = (uint32_t)(row * 128 + ((q ^ (row & 7)) * 16));
            int gr = row0 + row;
            int grc = (gr < N_NODES) ? gr : 0;
            uint32_t p = (gr < N_NODES) ? 16u : 0u;
            cp_async16(aB + sw, Ag + (size_t)grc * F + kc + q * 8, p);
            cp_async16(bB + sw, Bg + (size_t)row * F + kc + q * 8, 16u);
        }
        cp_commit();
    };

    auto compute = [&](int stg) {
        uint32_t aB = smb + stg * STAGE_BYTES;
        uint32_t bB = aB + 16384;
#pragma unroll
        for (int s = 0; s < 4; s++) {
            int ks = ((s + ko) & 3) * 16;   // staggered ks order per warp
            uint32_t af[2][4];
#pragma unroll
            for (int ms = 0; ms < 2; ms++) {
                int r = warp_m * 32 + ms * 16 + (lane & 15);
                int q = (ks >> 3) + (lane >> 4);
                ldm_x4(af[ms], aB + r * 128 + ((q ^ (r & 7)) * 16));
            }
            uint32_t bf[4][4];
#pragma unroll
            for (int np = 0; np < 4; np++) {
                int n = warp_n * 64 + np * 16 + (lane & 7) + ((lane >> 4) << 3);
                int q = (ks >> 3) + ((lane >> 3) & 1);
                ldm_x4(bf[np], bB + n * 128 + ((q ^ (n & 7)) * 16));
            }
#pragma unroll
            for (int ms = 0; ms < 2; ms++)
#pragma unroll
                for (int np = 0; np < 4; np++) {
                    mma_bf16(acc[ms][np * 2 + 0], af[ms], bf[np][0], bf[np][1]);
                    mma_bf16(acc[ms][np * 2 + 1], af[ms], bf[np][2], bf[np][3]);
                }
        }
    };

    load_chunk(0, 0);
    load_chunk(1, 1);
    for (int c = 0; c < DK_NCHUNK; c++) {
        if (c + 1 < DK_NCHUNK) cp_wait<1>(); else cp_wait<0>();
        __syncthreads();
        if (c + 2 < DK_NCHUNK) load_chunk(c + 2, (c + 2) % NSTAGE);
        compute(c % NSTAGE);
    }

#pragma unroll
    for (int ms = 0; ms < 2; ms++) {
#pragma unroll
        for (int half = 0; half < 2; half++) {
            int gr = row0 + warp_m * 32 + ms * 16 + (lane >> 2) + half * 8;
            if (gr >= N_NODES) continue;
#pragma unroll
            for (int np = 0; np < 8; np++) {
                int col = warp_n * 64 + np * 8 + (lane & 3) * 2;
                float v0 = acc[ms][np][half * 2 + 0] + s_bias[col];
                float v1 = acc[ms][np][half * 2 + 1] + s_bias[col + 1];
                if (do_relu) { v0 = fmaxf(v0, 0.f); v1 = fmaxf(v1, 0.f); }
                size_t gi = (size_t)gr * F + col;
                if (write_fp) {
                    *(float2*)(Ofp + gi) = make_float2(v0, v1);
                } else {
                    __nv_bfloat16 h0, l0, h1, l1;
                    split1(v0, h0, l0); split1(v1, h1, l1);
                    __nv_bfloat162 hh; hh.x = h0; hh.y = h1;
                    __nv_bfloat162 ll; ll.x = l0; ll.y = l1;
                    *(__nv_bfloat162*)(Ohi + gi) = hh;
                    *(__nv_bfloat162*)(Olo + gi) = ll;
                }
            }
        }
    }
}

// ---------------- launch -----------------------------------------------------
extern "C" void kernel_launch(void* const* d_in, const int* in_sizes, int n_in,
                              void* d_out, int out_size) {
    const float* feat = (const float*)d_in[0];
    const int*   src  = (const int*)d_in[1];
    const int*   dst  = (const int*)d_in[2];
    const float* Wsl[3] = {(const float*)d_in[3], (const float*)d_in[6], (const float*)d_in[9]};
    const float* Wnl[3] = {(const float*)d_in[4], (const float*)d_in[7], (const float*)d_in[10]};
    const float* bl[3]  = {(const float*)d_in[5], (const float*)d_in[8], (const float*)d_in[11]};
    float* out = (float*)d_out;

    __nv_bfloat16 *a0hi, *a0lo, *a1hi, *a1lo, *a2hi, *a2lo, *mhi, *mlo, *wts;
    cudaGetSymbolAddress((void**)&a0hi, g_a0hi);
    cudaGetSymbolAddress((void**)&a0lo, g_a0lo);
    cudaGetSymbolAddress((void**)&a1hi, g_a1hi);
    cudaGetSymbolAddress((void**)&a1lo, g_a1lo);
    cudaGetSymbolAddress((void**)&a2hi, g_a2hi);
    cudaGetSymbolAddress((void**)&a2lo, g_a2lo);
    cudaGetSymbolAddress((void**)&mhi,  g_mhi);
    cudaGetSymbolAddress((void**)&mlo,  g_mlo);
    cudaGetSymbolAddress((void**)&wts,  g_wts);

    const int DSM = NSTAGE * STAGE_BYTES;  // 96KB
    cudaFuncSetAttribute(sage_dual_gemm, cudaFuncAttributeMaxDynamicSharedMemorySize, DSM);

    const int TB = 256;
    const int aggGrid = (N_NODES * 32 + TB - 1) / TB;
    const int gmGrid  = (N_NODES + 127) / 128;
    const int n4 = N_NODES * F / 4;

    // CSR + prep (launch order as R8)
    fuse_zero_split_kernel<<<(n4 + TB - 1) / TB, TB>>>(feat, a0hi, a0lo);
    fuse_count_prep_kernel<<<(N_EDGES + TB - 1) / TB, TB>>>(
        dst, Wsl[0], Wnl[0], Wsl[1], Wnl[1], Wsl[2], Wnl[2], wts);
    assign_start_kernel<<<(N_NODES + TB - 1) / TB, TB>>>();
    fill_edges_kernel<<<(N_EDGES + TB - 1) / TB, TB>>>(src, dst);
    agg_f32_kernel<<<aggGrid, TB>>>(feat);

    // layer 1
    sage_dual_gemm<<<gmGrid, 256, DSM>>>(a0hi, a0lo, mhi, mlo, wts + 0 * 4 * F * F,
                                         bl[0], a1hi, a1lo, out, 1, 0);
    // layer 2
    agg_bf16_kernel<<<aggGrid, TB>>>(a1hi, a1lo);
    sage_dual_gemm<<<gmGrid, 256, DSM>>>(a1hi, a1lo, mhi, mlo, wts + 1 * 4 * F * F,
                                         bl[1], a2hi, a2lo, out, 1, 0);
    // layer 3
    agg_bf16_kernel<<<aggGrid, TB>>>(a2hi, a2lo);
    sage_dual_gemm<<<gmGrid, 256, DSM>>>(a2hi, a2lo, mhi, mlo, wts + 2 * 4 * F * F,
                                         bl[2], nullptr, nullptr, out, 0, 1);
}